// round 2
// baseline (speedup 1.0000x reference)
#include <cuda_runtime.h>

#define M 256
#define L 256
#define NWARP 8
#define HXc 3.0f
#define HZc 0.25f
#define JZc (-1.0f)
#define FULL 0xffffffffu

// ---- scratch (device globals; no allocations allowed) ----
__device__ float g_cos[M * L];
__device__ float g_sin[M * L];
__device__ float g_dN[M * L];   // sum_b base*(g_d*F + Gxz + Gzz)   (no factor 2)
__device__ float g_dD[M * L];   // sum_b base*g_d                   (no factor 2)
__device__ float g_dNc[M];      // sum_b coef[b]*P*F
__device__ float g_dDc[M];      // sum_b coef[b]*P
__device__ float g_Np[M];       // per-m partial of N
__device__ float g_Dp[M];       // per-m partial of D

__global__ void k_pre(const float* __restrict__ theta) {
    int i = blockIdx.x * blockDim.x + threadIdx.x;
    if (i < M * L) {
        float s, c;
        sincosf(theta[i], &s, &c);
        g_sin[i] = s;
        g_cos[i] = c;
    }
}

__global__ void __launch_bounds__(256, 2) k_main(const float* __restrict__ coef,
                                                 const float* __restrict__ strengths) {
    const int m    = blockIdx.x;
    const int tid  = threadIdx.x;
    const int w    = tid >> 5;
    const int lane = tid & 31;

    // per-thread fixed data: this block's row m, and edge strengths
    float cm[8], sm[8], se[8], sp[8];
#pragma unroll
    for (int j = 0; j < 8; j++) {
        int l = j * 32 + lane;
        cm[j] = g_cos[m * L + l];
        sm[j] = g_sin[m * L + l];
        se[j] = (l < L - 1) ? strengths[l] : 0.0f;   // edge (l, l+1)
        sp[j] = (l > 0)     ? strengths[l - 1] : 0.0f; // edge (l-1, l)
    }
    const float coefm = coef[m];

    float accN[8], accD[8];
#pragma unroll
    for (int j = 0; j < 8; j++) { accN[j] = 0.0f; accD[j] = 0.0f; }
    float accNc = 0.0f, accDc = 0.0f, accNp = 0.0f, accDp = 0.0f;

    // each warp handles b = w, w+8, ... (32 pairs per warp)
    for (int b = w; b < M; b += NWARP) {
        const float coefb = coef[b];
        float cb[8], sb[8], a[8], invv[8];
        float p = 1.0f, u = 0.0f, v = 0.0f;

#pragma unroll
        for (int j = 0; j < 8; j++) {
            int l = j * 32 + lane;
            cb[j] = g_cos[b * L + l];
            sb[j] = g_sin[b * L + l];
            float cc = cm[j] * cb[j];
            float ss = sm[j] * sb[j];
            float sc = sm[j] * cb[j];
            float cs = cm[j] * sb[j];
            float cosd = cc + ss;     // cos(tm - tb)
            float coss = cc - ss;     // cos(tm + tb)
            float sins = sc + cs;     // sin(tm + tb)
            float inv  = __fdividef(1.0f, cosd);
            invv[j] = inv;
            a[j]    = coss * inv;
            p *= cosd;
            u += sins * inv;
            v += a[j];
        }

        // neighbor values of a along the chain (strided lane layout l = j*32+lane)
        float an[8], ap[8];
#pragma unroll
        for (int j = 0; j < 8; j++) {
            float dn    = __shfl_down_sync(FULL, a[j], 1);
            float wrapn = __shfl_sync(FULL, a[(j + 1) & 7], 0);
            an[j] = (lane == 31) ? ((j < 7) ? wrapn : 0.0f) : dn;
            float up    = __shfl_up_sync(FULL, a[j], 1);
            float wrapp = __shfl_sync(FULL, a[(j + 7) & 7], 31);
            ap[j] = (lane == 0) ? ((j > 0) ? wrapp : 0.0f) : up;
        }

        float szz = 0.0f;
#pragma unroll
        for (int j = 0; j < 8; j++)
            szz += se[j] * a[j] * an[j];

        // warp-wide reductions: product P, sums U, V, Szz (xor: all lanes get result)
#pragma unroll
        for (int off = 16; off > 0; off >>= 1) {
            p   *= __shfl_xor_sync(FULL, p, off);
            u   += __shfl_xor_sync(FULL, u, off);
            v   += __shfl_xor_sync(FULL, v, off);
            szz += __shfl_xor_sync(FULL, szz, off);
        }

        const float F    = HZc * v + HXc * u + JZc * szz;
        const float base = coefm * coefb * p;
        accNc += coefb * p * F;
        accDc += coefb * p;
        accNp += base * F;
        accDp += base;

        // pass 2: theta-gradient contributions (recompute cheap trig products)
#pragma unroll
        for (int j = 0; j < 8; j++) {
            float cc = cm[j] * cb[j];
            float ss = sm[j] * sb[j];
            float sc = sm[j] * cb[j];
            float cs = cm[j] * sb[j];
            float coss = cc - ss;
            float sins = sc + cs;
            float sind = sc - cs;
            float inv  = invv[j];
            float g_d  = -sind * inv;
            float sii  = sind * inv * inv;
            float Gxz  = (HXc * coss - HZc * sins) * inv
                       + (HZc * coss + HXc * sins) * sii;
            float inc  = sp[j] * ap[j] + se[j] * an[j];
            float Gzz  = (coss * sii - sins * inv) * inc * JZc;
            accD[j] += base * g_d;
            accN[j] += base * (g_d * F + Gxz + Gzz);
        }
    }

    // cross-warp combine
    __shared__ float shN[NWARP * L];
    __shared__ float shD[NWARP * L];
    __shared__ float shS[NWARP][4];
#pragma unroll
    for (int j = 0; j < 8; j++) {
        shN[w * L + j * 32 + lane] = accN[j];
        shD[w * L + j * 32 + lane] = accD[j];
    }
    if (lane == 0) {
        shS[w][0] = accNc; shS[w][1] = accDc;
        shS[w][2] = accNp; shS[w][3] = accDp;
    }
    __syncthreads();

    float tN = 0.0f, tD = 0.0f;
#pragma unroll
    for (int ww = 0; ww < NWARP; ww++) {
        tN += shN[ww * L + tid];
        tD += shD[ww * L + tid];
    }
    g_dN[m * L + tid] = tN;
    g_dD[m * L + tid] = tD;

    if (tid == 0) {
        float a0 = 0.0f, a1 = 0.0f, a2 = 0.0f, a3 = 0.0f;
#pragma unroll
        for (int ww = 0; ww < NWARP; ww++) {
            a0 += shS[ww][0]; a1 += shS[ww][1];
            a2 += shS[ww][2]; a3 += shS[ww][3];
        }
        g_dNc[m] = a0; g_dDc[m] = a1;
        g_Np[m]  = a2; g_Dp[m]  = a3;
    }
}

__global__ void k_fin(float* __restrict__ out) {
    __shared__ float rn[256];
    __shared__ float rd[256];
    const int tid = threadIdx.x;
    rn[tid] = g_Np[tid];
    rd[tid] = g_Dp[tid];
    __syncthreads();
#pragma unroll
    for (int s = 128; s > 0; s >>= 1) {
        if (tid < s) { rn[tid] += rn[tid + s]; rd[tid] += rd[tid + s]; }
        __syncthreads();
    }
    const float N = rn[0];
    const float D = rd[0];
    const float E = N / D;

    if (blockIdx.x < M) {
        int idx = blockIdx.x * L + tid;
        out[idx] = (2.0f * g_dN[idx] - E * 2.0f * g_dD[idx]) / D;
    } else {
        out[M * L + tid] = (2.0f * g_dNc[tid] - E * 2.0f * g_dDc[tid]) / D;
        if (tid == 0) out[M * L + M] = E / (float)L;
    }
}

extern "C" void kernel_launch(void* const* d_in, const int* in_sizes, int n_in,
                              void* d_out, int out_size) {
    const float* theta     = (const float*)d_in[0];  // (M,L) f32
    const float* coef      = (const float*)d_in[1];  // (M,)  f32
    // d_in[2], d_in[3]: edges_u / edges_v (fixed 1D chain, encoded structurally)
    const float* strengths = (const float*)d_in[4];  // (L-1,) f32
    float* out = (float*)d_out;                      // [M*L | M | 1] f32

    k_pre <<<M, 256>>>(theta);
    k_main<<<M, 256>>>(coef, strengths);
    k_fin <<<M + 1, 256>>>(out);
}

// round 3
// speedup vs baseline: 1.0006x; 1.0006x over previous
#include <cuda_runtime.h>

#define M 256
#define L 256
#define NWARP 8
#define HXc 3.0f
#define HZc 0.25f
#define JZc (-1.0f)
#define FULL 0xffffffffu

// ---- scratch (device globals; no allocations allowed) ----
__device__ float g_cos[M * L];
__device__ float g_sin[M * L];
__device__ float g_dN[M * L];   // sum_b base*(g_d*F + Gxz + Gzz)   (no factor 2)
__device__ float g_dD[M * L];   // sum_b base*g_d                   (no factor 2)
__device__ float g_dNc[M];      // sum_b coef[b]*P*F
__device__ float g_dDc[M];      // sum_b coef[b]*P
__device__ float g_Np[M];       // per-m partial of N
__device__ float g_Dp[M];       // per-m partial of D

__global__ void k_pre(const float* __restrict__ theta) {
    int i = blockIdx.x * blockDim.x + threadIdx.x;
    if (i < M * L) {
        float s, c;
        sincosf(theta[i], &s, &c);
        g_sin[i] = s;
        g_cos[i] = c;
    }
}

__global__ void __launch_bounds__(256, 2) k_main(const float* __restrict__ coef,
                                                 const float* __restrict__ strengths) {
    const int m    = blockIdx.x;
    const int tid  = threadIdx.x;
    const int w    = tid >> 5;
    const int lane = tid & 31;

    // per-thread fixed data: this block's row m, and edge strengths
    float cm[8], sm[8], se[8], sp[8];
#pragma unroll
    for (int j = 0; j < 8; j++) {
        int l = j * 32 + lane;
        cm[j] = g_cos[m * L + l];
        sm[j] = g_sin[m * L + l];
        se[j] = (l < L - 1) ? strengths[l] : 0.0f;   // edge (l, l+1)
        sp[j] = (l > 0)     ? strengths[l - 1] : 0.0f; // edge (l-1, l)
    }
    const float coefm = coef[m];

    float accN[8], accD[8];
#pragma unroll
    for (int j = 0; j < 8; j++) { accN[j] = 0.0f; accD[j] = 0.0f; }
    float accNc = 0.0f, accDc = 0.0f, accNp = 0.0f, accDp = 0.0f;

    // each warp handles b = w, w+8, ... (32 pairs per warp)
    for (int b = w; b < M; b += NWARP) {
        const float coefb = coef[b];
        float cb[8], sb[8], a[8], invv[8];
        float p = 1.0f, u = 0.0f, v = 0.0f;

#pragma unroll
        for (int j = 0; j < 8; j++) {
            int l = j * 32 + lane;
            cb[j] = g_cos[b * L + l];
            sb[j] = g_sin[b * L + l];
            float cc = cm[j] * cb[j];
            float ss = sm[j] * sb[j];
            float sc = sm[j] * cb[j];
            float cs = cm[j] * sb[j];
            float cosd = cc + ss;     // cos(tm - tb)
            float coss = cc - ss;     // cos(tm + tb)
            float sins = sc + cs;     // sin(tm + tb)
            float inv  = __fdividef(1.0f, cosd);
            invv[j] = inv;
            a[j]    = coss * inv;
            p *= cosd;
            u += sins * inv;
            v += a[j];
        }

        // neighbor values of a along the chain (strided lane layout l = j*32+lane)
        float an[8], ap[8];
#pragma unroll
        for (int j = 0; j < 8; j++) {
            float dn    = __shfl_down_sync(FULL, a[j], 1);
            float wrapn = __shfl_sync(FULL, a[(j + 1) & 7], 0);
            an[j] = (lane == 31) ? ((j < 7) ? wrapn : 0.0f) : dn;
            float up    = __shfl_up_sync(FULL, a[j], 1);
            float wrapp = __shfl_sync(FULL, a[(j + 7) & 7], 31);
            ap[j] = (lane == 0) ? ((j > 0) ? wrapp : 0.0f) : up;
        }

        float szz = 0.0f;
#pragma unroll
        for (int j = 0; j < 8; j++)
            szz += se[j] * a[j] * an[j];

        // warp-wide reductions: product P, sums U, V, Szz (xor: all lanes get result)
#pragma unroll
        for (int off = 16; off > 0; off >>= 1) {
            p   *= __shfl_xor_sync(FULL, p, off);
            u   += __shfl_xor_sync(FULL, u, off);
            v   += __shfl_xor_sync(FULL, v, off);
            szz += __shfl_xor_sync(FULL, szz, off);
        }

        const float F    = HZc * v + HXc * u + JZc * szz;
        const float base = coefm * coefb * p;
        accNc += coefb * p * F;
        accDc += coefb * p;
        accNp += base * F;
        accDp += base;

        // pass 2: theta-gradient contributions (recompute cheap trig products)
#pragma unroll
        for (int j = 0; j < 8; j++) {
            float cc = cm[j] * cb[j];
            float ss = sm[j] * sb[j];
            float sc = sm[j] * cb[j];
            float cs = cm[j] * sb[j];
            float coss = cc - ss;
            float sins = sc + cs;
            float sind = sc - cs;
            float inv  = invv[j];
            float g_d  = -sind * inv;
            float sii  = sind * inv * inv;
            float Gxz  = (HXc * coss - HZc * sins) * inv
                       + (HZc * coss + HXc * sins) * sii;
            float inc  = sp[j] * ap[j] + se[j] * an[j];
            float Gzz  = (coss * sii - sins * inv) * inc * JZc;
            accD[j] += base * g_d;
            accN[j] += base * (g_d * F + Gxz + Gzz);
        }
    }

    // cross-warp combine
    __shared__ float shN[NWARP * L];
    __shared__ float shD[NWARP * L];
    __shared__ float shS[NWARP][4];
#pragma unroll
    for (int j = 0; j < 8; j++) {
        shN[w * L + j * 32 + lane] = accN[j];
        shD[w * L + j * 32 + lane] = accD[j];
    }
    if (lane == 0) {
        shS[w][0] = accNc; shS[w][1] = accDc;
        shS[w][2] = accNp; shS[w][3] = accDp;
    }
    __syncthreads();

    float tN = 0.0f, tD = 0.0f;
#pragma unroll
    for (int ww = 0; ww < NWARP; ww++) {
        tN += shN[ww * L + tid];
        tD += shD[ww * L + tid];
    }
    g_dN[m * L + tid] = tN;
    g_dD[m * L + tid] = tD;

    if (tid == 0) {
        float a0 = 0.0f, a1 = 0.0f, a2 = 0.0f, a3 = 0.0f;
#pragma unroll
        for (int ww = 0; ww < NWARP; ww++) {
            a0 += shS[ww][0]; a1 += shS[ww][1];
            a2 += shS[ww][2]; a3 += shS[ww][3];
        }
        g_dNc[m] = a0; g_dDc[m] = a1;
        g_Np[m]  = a2; g_Dp[m]  = a3;
    }
}

__global__ void k_fin(float* __restrict__ out) {
    __shared__ float rn[256];
    __shared__ float rd[256];
    const int tid = threadIdx.x;
    rn[tid] = g_Np[tid];
    rd[tid] = g_Dp[tid];
    __syncthreads();
#pragma unroll
    for (int s = 128; s > 0; s >>= 1) {
        if (tid < s) { rn[tid] += rn[tid + s]; rd[tid] += rd[tid + s]; }
        __syncthreads();
    }
    const float N = rn[0];
    const float D = rd[0];
    const float E = N / D;

    if (blockIdx.x < M) {
        int idx = blockIdx.x * L + tid;
        out[idx] = (2.0f * g_dN[idx] - E * 2.0f * g_dD[idx]) / D;
    } else {
        out[M * L + tid] = (2.0f * g_dNc[tid] - E * 2.0f * g_dDc[tid]) / D;
        if (tid == 0) out[M * L + M] = E / (float)L;
    }
}

extern "C" void kernel_launch(void* const* d_in, const int* in_sizes, int n_in,
                              void* d_out, int out_size) {
    const float* theta     = (const float*)d_in[0];  // (M,L) f32
    const float* coef      = (const float*)d_in[1];  // (M,)  f32
    // d_in[2], d_in[3]: edges_u / edges_v (fixed 1D chain, encoded structurally)
    const float* strengths = (const float*)d_in[4];  // (L-1,) f32
    float* out = (float*)d_out;                      // [M*L | M | 1] f32

    k_pre <<<M, 256>>>(theta);
    k_main<<<M, 256>>>(coef, strengths);
    k_fin <<<M + 1, 256>>>(out);
}